// round 4
// baseline (speedup 1.0000x reference)
#include <cuda_runtime.h>

// Problem constants (fixed by the dataset)
#define B_   128
#define D_   512
#define KP_  2048        // K + num_positive
#define NF_  16084
#define NP_  604731
#define INV_T 14.2857142857142857f   // 1 / 0.07

// Deterministic per-b loss partials (no float atomics)
__device__ float g_partial[B_];

// ---------------------------------------------------------------------------
// Kernel 1: copy one memory bank into the output region.
// dst = d_out + 1 + bank_offset, which is 4B-offset from 16B alignment when
// out is 16B-aligned. We therefore vectorize on the DESTINATION: each thread
// handles 4 consecutive dst elements starting at j ≡ PRO (mod 4) so the
// STG is .128; the 4 loads are scalar but aggregate-coalesced (all sectors
// of each 128B line touched by the warp). Scalar prologue/epilogue.
// ---------------------------------------------------------------------------
__global__ void __launch_bounds__(256) copy_bank(const float* __restrict__ src,
                                                 float* __restrict__ dst,
                                                 long long n)
{
    // Alignment of dst: dst = out + 1 (+ NF*D which is a multiple of 4).
    // (uintptr)dst % 16 == 4  =>  first 16B-aligned element is j = 3.
    const long long PRO = 3;
    const long long nv = (n - PRO) >> 2;   // number of float4 chunks
    const long long stride = (long long)gridDim.x * blockDim.x;
    const long long tid0 = (long long)blockIdx.x * blockDim.x + threadIdx.x;

    // prologue (3 elements)
    if (tid0 < PRO) dst[tid0] = src[tid0];

    for (long long v = tid0; v < nv; v += stride) {
        const long long j = PRO + 4 * v;
        float4 r;
        r.x = src[j + 0];
        r.y = src[j + 1];
        r.z = src[j + 2];
        r.w = src[j + 3];
        *(float4*)(dst + j) = r;
    }

    // epilogue (up to 3 elements)
    const long long tail = PRO + 4 * nv;
    const long long t = tail + tid0;
    if (t < n) dst[t] = src[t];
}

// ---------------------------------------------------------------------------
// Kernel 2: contrastive loss. One block per batch element b.
// 16 warps; warp w handles gathered rows k = w, w+16, ... over the 2*KP=4096
// concatenated columns (k < KP -> mem1[idx1], else mem2[idx2]).
// Each lane keeps v1[b]/v2[b] slices in registers (4x float4 each) -> no LDS
// in the hot loop. Per row: 4 LDG.128 + 32 FFMA per lane, warp shfl-reduce,
// then per-warp online softmax (t=0 and t=1 simultaneously).
// ---------------------------------------------------------------------------
__global__ void __launch_bounds__(512) loss_kernel(const float* __restrict__ v1,
                                                   const float* __restrict__ v2,
                                                   const int*   __restrict__ idx1,
                                                   const int*   __restrict__ idx2,
                                                   const float* __restrict__ mem1,
                                                   const float* __restrict__ mem2)
{
    const int b    = blockIdx.x;
    const int tid  = threadIdx.x;
    const int warp = tid >> 5;
    const int lane = tid & 31;
    const int NW   = 16;  // 512 / 32

    __shared__ float sm_m1[NW], sm_s1[NW], sm_m2[NW], sm_s2[NW];
    __shared__ float spos[4];   // l(t=0,k=0), l(t=1,k=0), l(t=0,k=KP), l(t=1,k=KP)

    // v1[b], v2[b] into registers: lane covers d = 128*c + 4*lane + {0..3}
    float4 rv1[4], rv2[4];
#pragma unroll
    for (int c = 0; c < 4; c++) {
        rv1[c] = *(const float4*)(v1 + (size_t)b * D_ + 128 * c + 4 * lane);
        rv2[c] = *(const float4*)(v2 + (size_t)b * D_ + 128 * c + 4 * lane);
    }

    float m1 = -1e30f, s1 = 0.0f;
    float m2 = -1e30f, s2 = 0.0f;

    for (int k = warp; k < 2 * KP_; k += NW) {
        const float* __restrict__ wrow;
        if (k < KP_) {
            wrow = mem1 + (size_t)__ldg(idx1 + b * KP_ + k) * D_;
        } else {
            wrow = mem2 + (size_t)__ldg(idx2 + b * KP_ + (k - KP_)) * D_;
        }

        float a1 = 0.0f, a2 = 0.0f;
#pragma unroll
        for (int c = 0; c < 4; c++) {
            float4 w = *(const float4*)(wrow + 128 * c + 4 * lane);
            a1 += w.x * rv1[c].x + w.y * rv1[c].y + w.z * rv1[c].z + w.w * rv1[c].w;
            a2 += w.x * rv2[c].x + w.y * rv2[c].y + w.z * rv2[c].z + w.w * rv2[c].w;
        }
        // warp butterfly reduce (both dots)
#pragma unroll
        for (int off = 16; off; off >>= 1) {
            a1 += __shfl_xor_sync(0xffffffffu, a1, off);
            a2 += __shfl_xor_sync(0xffffffffu, a2, off);
        }
        a1 *= INV_T;
        a2 *= INV_T;

        if (lane == 0) {
            if (k == 0)   { spos[0] = a1; spos[1] = a2; }
            if (k == KP_) { spos[2] = a1; spos[3] = a2; }
        }

        // online softmax update (identical across lanes; cheap)
        float nm = fmaxf(m1, a1);
        s1 = s1 * __expf(m1 - nm) + __expf(a1 - nm);
        m1 = nm;
        nm = fmaxf(m2, a2);
        s2 = s2 * __expf(m2 - nm) + __expf(a2 - nm);
        m2 = nm;
    }

    if (lane == 0) {
        sm_m1[warp] = m1; sm_s1[warp] = s1;
        sm_m2[warp] = m2; sm_s2[warp] = s2;
    }
    __syncthreads();

    if (tid == 0) {
        float M1 = -1e30f, M2 = -1e30f;
        for (int w = 0; w < NW; w++) {
            M1 = fmaxf(M1, sm_m1[w]);
            M2 = fmaxf(M2, sm_m2[w]);
        }
        float S1 = 0.0f, S2 = 0.0f;
        for (int w = 0; w < NW; w++) {
            S1 += sm_s1[w] * expf(sm_m1[w] - M1);
            S2 += sm_s2[w] * expf(sm_m2[w] - M2);
        }
        float lse1 = M1 + logf(S1);
        float lse2 = M2 + logf(S2);
        // per-b: sum over t of mean_log_prob_pos
        float contrib = 0.5f * (spos[0] + spos[2]) - lse1
                      + 0.5f * (spos[1] + spos[3]) - lse2;
        g_partial[b] = contrib;
    }
}

// ---------------------------------------------------------------------------
// Kernel 3: momentum update of the 2*B touched rows (overwrites copied rows)
// + deterministic loss finalize (block 2*B_).
// Duplicate labels: emulate scatter "last update wins".
// ---------------------------------------------------------------------------
__global__ void __launch_bounds__(128) update_kernel(const float* __restrict__ v1,
                                                     const int*   __restrict__ y1,
                                                     const float* __restrict__ v2,
                                                     const int*   __restrict__ y2,
                                                     const float* __restrict__ mem1,
                                                     const float* __restrict__ mem2,
                                                     float* __restrict__ out)
{
    const int blk = blockIdx.x;

    if (blk == 2 * B_) {  // loss finalize
        if (threadIdx.x == 0) {
            float s = 0.0f;
            for (int i = 0; i < B_; i++) s += g_partial[i];
            out[0] = -s / (2.0f * B_);
        }
        return;
    }

    const int bank = blk / B_;   // 0 -> mem1, 1 -> mem2
    const int b    = blk % B_;

    const int*   __restrict__ y   = bank ? y2 : y1;
    const float* __restrict__ v   = bank ? v2 : v1;
    const float* __restrict__ mem = bank ? mem2 : mem1;
    float* __restrict__ dst = out + 1 + (bank ? (size_t)NF_ * D_ : (size_t)0);

    const int row = __ldg(y + b);
    // last-occurrence-wins: skip if a later b' writes the same row
    for (int b2 = b + 1; b2 < B_; b2++)
        if (__ldg(y + b2) == row) return;   // uniform across block

    const int tid = threadIdx.x;
    float p[4];
    float ss = 0.0f;
#pragma unroll
    for (int j = 0; j < 4; j++) {
        int d = tid + j * 128;
        float x = 0.5f * __ldg(mem + (size_t)row * D_ + d)
                + 0.5f * __ldg(v + (size_t)b * D_ + d);
        p[j] = x;
        ss += x * x;
    }
#pragma unroll
    for (int off = 16; off; off >>= 1)
        ss += __shfl_xor_sync(0xffffffffu, ss, off);

    __shared__ float wsum[4];
    if ((tid & 31) == 0) wsum[tid >> 5] = ss;
    __syncthreads();
    float tot = wsum[0] + wsum[1] + wsum[2] + wsum[3];
    float inv = 1.0f / sqrtf(tot);

#pragma unroll
    for (int j = 0; j < 4; j++) {
        int d = tid + j * 128;
        dst[(size_t)row * D_ + d] = p[j] * inv;
    }
}

// ---------------------------------------------------------------------------
// Launch
// inputs: 0 v1(f32 B*D) 1 y1(i32 B) 2 v2 3 y2 4 idx1(i32 B*KP) 5 idx2
//         6 memory_v1(f32 NF*D) 7 memory_v2(f32 NP*D)
// output: [loss, new_mem_v1 (NF*D), new_mem_v2 (NP*D)]
// ---------------------------------------------------------------------------
extern "C" void kernel_launch(void* const* d_in, const int* in_sizes, int n_in,
                              void* d_out, int out_size)
{
    (void)in_sizes; (void)n_in; (void)out_size;
    const float* v1   = (const float*)d_in[0];
    const int*   y1   = (const int*)  d_in[1];
    const float* v2   = (const float*)d_in[2];
    const int*   y2   = (const int*)  d_in[3];
    const int*   idx1 = (const int*)  d_in[4];
    const int*   idx2 = (const int*)  d_in[5];
    const float* mem1 = (const float*)d_in[6];
    const float* mem2 = (const float*)d_in[7];
    float* out = (float*)d_out;

    const long long N1 = (long long)NF_ * D_;
    const long long N2 = (long long)NP_ * D_;

    copy_bank<<<2368, 256>>>(mem1, out + 1, N1);
    copy_bank<<<4736, 256>>>(mem2, out + 1 + N1, N2);
    loss_kernel<<<B_, 512>>>(v1, v2, idx1, idx2, mem1, mem2);
    update_kernel<<<2 * B_ + 1, 128>>>(v1, y1, v2, y2, mem1, mem2, out);
}